// round 12
// baseline (speedup 1.0000x reference)
#include <cuda_runtime.h>
#include <cuda_bf16.h>
#include <math.h>
#include <stdint.h>

typedef uint32_t u32;
typedef unsigned long long u64;

#define TT 256
#define BB 256
#define HH 1024
#define N2 2048
#define BMH (BB*HH)
#define NTHR 512                 /* 16 warps/CTA, 1 CTA/SM -> 4 warps/SMSP */
#define PTHR 256                 /* prep kernel threads */
#define GBLK 128
#define CHU 1024                 /* uint4 per 16KB image block */
#define SMEMT 98304              /* 2 x 48KB chunk buffers (T64) */
#define SWZ(o) ((o) ^ (((o) >> 3) & 0x70))

/* fp32 states s0..s8 */
__device__ float g_S[9][BMH];
/* bf16 hi/lo swizzled images */
__device__ uint4 g_Sih[288 * CHU], g_Sil[288 * CHU];
__device__ uint4 g_Xh[32 * CHU],  g_Xl[32 * CHU];
__device__ uint4 g_Hh[32 * CHU],  g_Hl[32 * CHU];
__device__ uint4 g_W0h[512 * CHU], g_W0l[512 * CHU];
__device__ uint4 g_Wsh[2048 * CHU], g_Wsl[2048 * CHU];
__device__ u64 g_bar;

/* ---------------- helpers ---------------- */
__device__ __forceinline__ float sigf(float v) { return 1.0f / (1.0f + expf(-v)); }
__device__ __forceinline__ float actf(float v, int a) {
    switch (a) { case 0: return sigf(v); case 1: return fmaxf(v, 0.0f);
                 case 2: return tanhf(v); default: return v; }
}
__device__ __forceinline__ u32 smem_u32(const void* p) {
    u32 a; asm("{ .reg .u64 t; cvta.to.shared.u64 t, %1; cvt.u32.u64 %0, t; }" : "=r"(a) : "l"(p));
    return a;
}
__device__ __forceinline__ void split8(const float* v, uint4& hi, uint4& lo) {
    u32 h[4], l[4];
#pragma unroll
    for (int p = 0; p < 4; p++) {
        __nv_bfloat16 b0 = __float2bfloat16(v[2*p]);
        __nv_bfloat16 b1 = __float2bfloat16(v[2*p+1]);
        __nv_bfloat16 c0 = __float2bfloat16(v[2*p]   - __bfloat162float(b0));
        __nv_bfloat16 c1 = __float2bfloat16(v[2*p+1] - __bfloat162float(b1));
        h[p] = (u32)__bfloat16_as_ushort(b0) | ((u32)__bfloat16_as_ushort(b1) << 16);
        l[p] = (u32)__bfloat16_as_ushort(c0) | ((u32)__bfloat16_as_ushort(c1) << 16);
    }
    hi = make_uint4(h[0], h[1], h[2], h[3]);
    lo = make_uint4(l[0], l[1], l[2], l[3]);
}
__device__ __forceinline__ void split2(float s0, float s1, u32& hi, u32& lo) {
    __nv_bfloat16 b0 = __float2bfloat16(s0), b1 = __float2bfloat16(s1);
    __nv_bfloat16 c0 = __float2bfloat16(s0 - __bfloat162float(b0));
    __nv_bfloat16 c1 = __float2bfloat16(s1 - __bfloat162float(b1));
    hi = (u32)__bfloat16_as_ushort(b0) | ((u32)__bfloat16_as_ushort(b1) << 16);
    lo = (u32)__bfloat16_as_ushort(c0) | ((u32)__bfloat16_as_ushort(c1) << 16);
}

/* ---------------- warp MMA primitives ---------------- */
__device__ __forceinline__ void ldsm4(u32* d, u32 a) {
    asm volatile("ldmatrix.sync.aligned.m8n8.x4.shared.b16 {%0,%1,%2,%3}, [%4];"
        : "=r"(d[0]), "=r"(d[1]), "=r"(d[2]), "=r"(d[3]) : "r"(a));
}
__device__ __forceinline__ void ldsm2(u32* d, u32 a) {
    asm volatile("ldmatrix.sync.aligned.m8n8.x2.shared.b16 {%0,%1}, [%2];"
        : "=r"(d[0]), "=r"(d[1]) : "r"(a));
}
__device__ __forceinline__ void mma16816(float* c, const u32* a, const u32* b) {
    asm volatile("mma.sync.aligned.m16n8k16.row.col.f32.bf16.bf16.f32 "
        "{%0,%1,%2,%3}, {%4,%5,%6,%7}, {%8,%9}, {%0,%1,%2,%3};"
        : "+f"(c[0]), "+f"(c[1]), "+f"(c[2]), "+f"(c[3])
        : "r"(a[0]), "r"(a[1]), "r"(a[2]), "r"(a[3]), "r"(b[0]), "r"(b[1]));
}
#define CPA(dst, src) asm volatile("cp.async.cg.shared.global [%0], [%1], 16;" :: "r"(dst), "l"(src))
#define CPCOMMIT()    asm volatile("cp.async.commit_group;" ::: "memory")
#define CPWAIT(n)     asm volatile("cp.async.wait_group %0;" :: "n"(n) : "memory")

/* ---------------- grid barrier ---------------- */
__device__ __forceinline__ void gridbar() {
    __threadfence();
    __syncthreads();
    if (threadIdx.x == 0) {
        u64 t = atomicAdd(&g_bar, 1ULL);
        u64 goal = (t / GBLK + 1ULL) * (u64)GBLK;
        u64 v;
        do { asm volatile("ld.acquire.gpu.u64 %0, [%1];" : "=l"(v) : "l"(&g_bar) : "memory"); }
        while (v < goal);
    }
    __syncthreads();
}

/* ---------------- prep: build swizzled bf16 hi/lo images (verified) ---------------- */
__global__ __launch_bounds__(PTHR) void prep(
    const float* __restrict__ inputs, const float* __restrict__ h0,
    const float* __restrict__ W0, const float* __restrict__ Ws)
{
    __shared__ float s[64][129];
    const int b = blockIdx.x, tid = threadIdx.x;

    if (b < 2560) {
        const float* Wsrc; int nt, kc; uint4 *dh, *dl;
        if (b < 512) {
            nt = b >> 5; kc = b & 31; Wsrc = W0;
            dh = g_W0h + (size_t)b * CHU; dl = g_W0l + (size_t)b * CHU;
        } else {
            int b2 = b - 512;
            nt = (b2 >> 4) & 15; kc = b2 & 15;
            Wsrc = Ws + (size_t)(b2 >> 8) * HH * N2;
            dh = g_Wsh + (size_t)b2 * CHU; dl = g_Wsl + (size_t)b2 * CHU;
        }
        for (int i = tid; i < 64 * 128; i += PTHR) {
            int k = i >> 7, r = i & 127;
            int n = (r < 64) ? nt * 64 + r : HH + nt * 64 + (r - 64);
            s[k][r] = Wsrc[(size_t)(kc * 64 + k) * N2 + n];
        }
        __syncthreads();
        for (int uu = tid; uu < 1024; uu += PTHR) {
            int r = uu >> 3, g = uu & 7;
            float v[8];
#pragma unroll
            for (int i = 0; i < 8; i++) v[i] = s[g * 8 + i][r];
            uint4 hi, lo; split8(v, hi, lo);
            u32 off = SWZ((u32)(r * 128 + g * 16));
            dh[off >> 4] = hi; dl[off >> 4] = lo;
        }
    } else {
        int b3 = b - 2560;
        const float* src = (b3 < 128) ? inputs : h0;
        uint4* dh = (b3 < 128) ? g_Xh : g_Hh;
        uint4* dl = (b3 < 128) ? g_Xl : g_Hl;
        int uu = (b3 & 127) * PTHR + tid;
        int g = uu & 7, r = (uu >> 3) & 127, kc = (uu >> 10) & 15, mt = uu >> 14;
        int m = mt * 128 + r, k = kc * 64 + g * 8;
        const float4* p = (const float4*)(src + (size_t)m * HH + k);
        float4 a = p[0], bq = p[1];
        float v[8] = {a.x, a.y, a.z, a.w, bq.x, bq.y, bq.z, bq.w};
        uint4 hi, lo; split8(v, hi, lo);
        u32 off = SWZ((u32)(r * 128 + g * 16));
        size_t blk = (size_t)(mt * 16 + kc) * CHU;
        dh[blk + (off >> 4)] = hi; dl[blk + (off >> 4)] = lo;
    }
}

/* ---------------- fused full-K GEMM tile + DARTS epilogue, 16 warps ----------------
 * MT rows x 64-j block (64 c || 64 h). Warp grid: T64 4x4 (NFC=2), T32 2x8 (NFC=1).
 * Each warp owns a 16-row m-frag. 3-pass bf16 hi/lo compensation. */
template<int MT>
__device__ __noinline__ void run_tile(
    u32 sbase,
    const uint4* __restrict__ Ah0, const uint4* __restrict__ Al0,
    const uint4* __restrict__ Ah1, const uint4* __restrict__ Al1,
    int n1, int nchunks, int rowoff,
    const uint4* __restrict__ Wh, const uint4* __restrict__ Wl,
    const float* __restrict__ sp, float* __restrict__ Sout,
    uint4* imgH, uint4* imgL, int act, int m0, int j0)
{
    constexpr int WN  = (MT == 64) ? 4 : 8;   /* warps along N */
    constexpr int NFC = (MT == 64) ? 2 : 1;   /* n8 c-frags per warp */
    constexpr int JW  = 64 / WN;              /* j-cols per warp */
    constexpr int BS  = 2 * MT * 128 + 32768; /* bytes per chunk buffer */
    const int tid = threadIdx.x, lid = tid & 31, wid = tid >> 5;
    const int wm = wid / WN, wn = wid % WN;
    const int ncw = wn * JW;

    float accC[NFC][4], accH[NFC][4];
#pragma unroll
    for (int j = 0; j < NFC; j++)
#pragma unroll
        for (int q = 0; q < 4; q++) { accC[j][q] = 0.f; accH[j][q] = 0.f; }

    const int arl = (lid & 7) + ((lid >> 3) & 1) * 8;
    const u32 aXor = (u32)((lid & 7) << 4);
    const u32 aK = (u32)((lid >> 4) * 16);
    const int lb = lid & 15;
    const u32 bXor = (u32)((lb & 7) << 4);
    const u32 bK = (u32)(((lb >> 3) & 1) * 16);
    const int brl = lb & 7;

    auto issue = [&](int c, int buf) {
        const uint4* Ahc = (c < n1) ? (Ah0 + (size_t)c * CHU) : (Ah1 + (size_t)(c - n1) * CHU);
        const uint4* Alc = (c < n1) ? (Al0 + (size_t)c * CHU) : (Al1 + (size_t)(c - n1) * CHU);
        const uint4* Wch = Wh + (size_t)c * CHU;
        const uint4* Wcl = Wl + (size_t)c * CHU;
        u32 d = sbase + (u32)buf * BS;
        if (tid < MT * 8) {   /* A hi + A lo: MT*8 uint4 each */
            CPA(d + (u32)tid * 16u, (const void*)(Ahc + rowoff + tid));
            CPA(d + (u32)MT * 128u + (u32)tid * 16u, (const void*)(Alc + rowoff + tid));
        }
        u32 wb = d + 2u * (u32)MT * 128u;
#pragma unroll
        for (int i = 0; i < 2; i++) {
            CPA(wb + (u32)(tid + i * NTHR) * 16u, (const void*)(Wch + tid + i * NTHR));
            CPA(wb + 16384u + (u32)(tid + i * NTHR) * 16u, (const void*)(Wcl + tid + i * NTHR));
        }
        CPCOMMIT();
    };

    issue(0, 0);
    if (nchunks > 1) issue(1, 1);
    int buf = 0;
    for (int ci = 0; ci < nchunks; ci++) {
        if (ci < nchunks - 1) { CPWAIT(1); } else { CPWAIT(0); }
        __syncthreads();
        u32 b0 = sbase + (u32)buf * BS;
        u32 wB = b0 + 2u * MT * 128;
#pragma unroll
        for (int ks = 0; ks < 4; ks++) {
            u32 ah[4], al[4];
            u32 ka = ((u32)(ks * 32) + aK) ^ aXor;
            u32 ad = b0 + (u32)((wm * 16 + arl) * 128) + ka;
            ldsm4(ah, ad);
            ldsm4(al, ad + (u32)MT * 128);
            u32 kb = ((u32)(ks * 32) + bK) ^ bXor;
            u32 bhC[NFC][2], blC[NFC][2], bhH[NFC][2], blH[NFC][2];
#pragma unroll
            for (int nf = 0; nf < NFC; nf++) {
                u32 bc = wB + (u32)((ncw + nf * 8 + brl) * 128) + kb;
                ldsm2(bhC[nf], bc); ldsm2(blC[nf], bc + 16384u);
                u32 bh = wB + (u32)((64 + ncw + nf * 8 + brl) * 128) + kb;
                ldsm2(bhH[nf], bh); ldsm2(blH[nf], bh + 16384u);
            }
#pragma unroll
            for (int nf = 0; nf < NFC; nf++) {
                mma16816(accC[nf], ah, bhC[nf]);
                mma16816(accC[nf], ah, blC[nf]);
                mma16816(accC[nf], al, bhC[nf]);
                mma16816(accH[nf], ah, bhH[nf]);
                mma16816(accH[nf], ah, blH[nf]);
                mma16816(accH[nf], al, bhH[nf]);
            }
        }
        __syncthreads();
        if (ci + 2 < nchunks) issue(ci + 2, buf);
        buf ^= 1;
    }

    /* fused epilogue */
#pragma unroll
    for (int nf = 0; nf < NFC; nf++) {
        int rb = m0 + wm * 16 + (lid >> 2);
        int j = j0 + ncw + nf * 8 + (lid & 3) * 2;
#pragma unroll
        for (int hr = 0; hr < 2; hr++) {
            int r = rb + hr * 8;
            float cv0 = accC[nf][hr * 2 + 0], cv1 = accC[nf][hr * 2 + 1];
            float hv0 = accH[nf][hr * 2 + 0], hv1 = accH[nf][hr * 2 + 1];
            float2 spv = *(const float2*)(sp + (size_t)r * HH + j);
            float s0 = spv.x + sigf(cv0) * (actf(hv0, act) - spv.x);
            float s1 = spv.y + sigf(cv1) * (actf(hv1, act) - spv.y);
            *(float2*)(Sout + (size_t)r * HH + j) = make_float2(s0, s1);
            if (imgH) {
                u32 hi, lo; split2(s0, s1, hi, lo);
                u32 off = SWZ((u32)((r & 127) * 128 + (j & 63) * 2));
                *(u32*)((char*)imgH + off) = hi;
                *(u32*)((char*)imgL + off) = lo;
            }
        }
    }
}

/* ---------------- persistent kernel ---------------- */
__global__ __launch_bounds__(NTHR, 1) void darts_mma(
    const float* __restrict__ inputs, const float* __restrict__ h0,
    float* __restrict__ out)
{
    extern __shared__ char smem[];
    const u32 sbase = smem_u32(smem);
    const int tid = threadIdx.x, bid = blockIdx.x;

    for (int t = 0; t < TT; t++) {
        const float* hp = t ? (out + (size_t)(t - 1) * BMH) : h0;

        /* Phase A: s0 over concat(x, h_prev), K=2048. 128 T32 tasks, tanh. */
        {
            int m0 = (bid >> 4) * 32, nt = bid & 15, mtb = m0 >> 7, ro = (m0 & 127) * 8;
            run_tile<32>(sbase,
                g_Xh + (size_t)mtb * 16 * CHU, g_Xl + (size_t)mtb * 16 * CHU,
                g_Hh + (size_t)mtb * 16 * CHU, g_Hl + (size_t)mtb * 16 * CHU,
                16, 32, ro,
                g_W0h + (size_t)nt * 32 * CHU, g_W0l + (size_t)nt * 32 * CHU,
                hp, g_S[0],
                g_Sih + ((size_t)mtb * 16 + nt) * CHU,
                g_Sil + ((size_t)mtb * 16 + nt) * CHU, 2, m0, nt * 64);
        }
        gridbar();

        /* Phase B: s1 = f(s0, Ws0, sigmoid). 128 T32 tasks, K=1024. */
        {
            int m0 = (bid >> 4) * 32, nt = bid & 15, mtb = m0 >> 7, ro = (m0 & 127) * 8;
            run_tile<32>(sbase,
                g_Sih + (size_t)mtb * 16 * CHU, g_Sil + (size_t)mtb * 16 * CHU,
                (const uint4*)0, (const uint4*)0, 16, 16, ro,
                g_Wsh + (size_t)nt * 16 * CHU, g_Wsl + (size_t)nt * 16 * CHU,
                g_S[0], g_S[1],
                g_Sih + ((size_t)(32 + mtb * 16 + nt)) * CHU,
                g_Sil + ((size_t)(32 + mtb * 16 + nt)) * CHU, 0, m0, nt * 64);
        }
        gridbar();

        /* Phase C: s2 (bid<64) / s3 (bid>=64) from s1. 128 T64 tasks, relu. */
        {
            int op = bid >> 6, sub = bid & 63;
            int m0 = (sub >> 4) * 64, nt = sub & 15, mtb = m0 >> 7, ro = (m0 & 127) * 8;
            int os = 2 + op;
            run_tile<64>(sbase,
                g_Sih + (size_t)(32 + mtb * 16) * CHU, g_Sil + (size_t)(32 + mtb * 16) * CHU,
                (const uint4*)0, (const uint4*)0, 16, 16, ro,
                g_Wsh + (size_t)((1 + op) * 256 + nt * 16) * CHU,
                g_Wsl + (size_t)((1 + op) * 256 + nt * 16) * CHU,
                g_S[1], g_S[os],
                g_Sih + ((size_t)(os * 32 + mtb * 16 + nt)) * CHU,
                g_Sil + ((size_t)(os * 32 + mtb * 16 + nt)) * CHU, 1, m0, nt * 64);
        }
        gridbar();

        /* Phase D: s5<-s2 / s7<-s3 (T64, tanh), then s4<-s1 (T32, identity). */
        {
            int op = bid >> 6, sub = bid & 63;
            int m0 = (sub >> 4) * 64, nt = sub & 15, mtb = m0 >> 7, ro = (m0 & 127) * 8;
            int is = op ? 3 : 2, os = op ? 7 : 5, wop = op ? 6 : 4;
            uint4* ih = op ? (uint4*)0 : g_Sih + ((size_t)(5 * 32 + mtb * 16 + nt)) * CHU;
            uint4* il = op ? (uint4*)0 : g_Sil + ((size_t)(5 * 32 + mtb * 16 + nt)) * CHU;
            run_tile<64>(sbase,
                g_Sih + (size_t)(is * 32 + mtb * 16) * CHU, g_Sil + (size_t)(is * 32 + mtb * 16) * CHU,
                (const uint4*)0, (const uint4*)0, 16, 16, ro,
                g_Wsh + (size_t)(wop * 256 + nt * 16) * CHU,
                g_Wsl + (size_t)(wop * 256 + nt * 16) * CHU,
                g_S[is], g_S[os], ih, il, 2, m0, nt * 64);

            int m0b = (bid >> 4) * 32, ntb = bid & 15, mtb2 = m0b >> 7, rob = (m0b & 127) * 8;
            run_tile<32>(sbase,
                g_Sih + (size_t)(32 + mtb2 * 16) * CHU, g_Sil + (size_t)(32 + mtb2 * 16) * CHU,
                (const uint4*)0, (const uint4*)0, 16, 16, rob,
                g_Wsh + (size_t)(3 * 256 + ntb * 16) * CHU,
                g_Wsl + (size_t)(3 * 256 + ntb * 16) * CHU,
                g_S[1], g_S[4], (uint4*)0, (uint4*)0, 3, m0b, ntb * 64);
        }
        gridbar();

        /* Phase E: s6<-s5 (sigmoid) / s8<-s5 (relu). 128 T64 tasks. */
        {
            int op = bid >> 6, sub = bid & 63;
            int m0 = (sub >> 4) * 64, nt = sub & 15, mtb = m0 >> 7, ro = (m0 & 127) * 8;
            int os = op ? 8 : 6, wop = op ? 7 : 5, a = op ? 1 : 0;
            run_tile<64>(sbase,
                g_Sih + (size_t)(5 * 32 + mtb * 16) * CHU, g_Sil + (size_t)(5 * 32 + mtb * 16) * CHU,
                (const uint4*)0, (const uint4*)0, 16, 16, ro,
                g_Wsh + (size_t)(wop * 256 + nt * 16) * CHU,
                g_Wsl + (size_t)(wop * 256 + nt * 16) * CHU,
                g_S[5], g_S[os], (uint4*)0, (uint4*)0, a, m0, nt * 64);
        }
        gridbar();

        /* Phase F: out[t] = mean(s1..s8); emit h image; convert x_{t+1} image.
           65536 threads x 4 floats each. */
        {
            float* ot = out + (size_t)t * BMH;
            int uu = bid * NTHR + tid;
            int m = uu >> 8, j = (uu & 255) * 4;
            float a[4] = {0.f, 0.f, 0.f, 0.f};
#pragma unroll
            for (int s = 1; s < 9; s++) {
                float4 v = *(const float4*)(&g_S[s][(size_t)m * HH + j]);
                a[0] += v.x; a[1] += v.y; a[2] += v.z; a[3] += v.w;
            }
#pragma unroll
            for (int q = 0; q < 4; q++) a[q] *= 0.125f;
            *(float4*)(ot + (size_t)m * HH + j) = make_float4(a[0], a[1], a[2], a[3]);
            {
                u32 h0w, l0w, h1w, l1w;
                split2(a[0], a[1], h0w, l0w);
                split2(a[2], a[3], h1w, l1w);
                u32 off = SWZ((u32)((m & 127) * 128 + (j & 63) * 2));
                size_t blk = ((size_t)(m >> 7) * 16 + (j >> 6)) * CHU;
                *(uint2*)((char*)(g_Hh + blk) + off) = make_uint2(h0w, h1w);
                *(uint2*)((char*)(g_Hl + blk) + off) = make_uint2(l0w, l1w);
            }
            if (t + 1 < TT) {
                float4 v = *(const float4*)(inputs + (size_t)(t + 1) * BMH + (size_t)m * HH + j);
                u32 h0w, l0w, h1w, l1w;
                split2(v.x, v.y, h0w, l0w);
                split2(v.z, v.w, h1w, l1w);
                u32 off = SWZ((u32)((m & 127) * 128 + (j & 63) * 2));
                size_t blk = ((size_t)(m >> 7) * 16 + (j >> 6)) * CHU;
                *(uint2*)((char*)(g_Xh + blk) + off) = make_uint2(h0w, h1w);
                *(uint2*)((char*)(g_Xl + blk) + off) = make_uint2(l0w, l1w);
            }
        }
        gridbar();
    }
}

extern "C" void kernel_launch(void* const* d_in, const int* in_sizes, int n_in,
                              void* d_out, int out_size)
{
    const float* inputs = (const float*)d_in[0];  /* [T, B, 1024] */
    const float* h0     = (const float*)d_in[1];  /* [B, 1024]    */
    const float* W0     = (const float*)d_in[2];  /* [2048, 2048] */
    const float* Ws     = (const float*)d_in[3];  /* [8, 1024, 2048] */
    float* out = (float*)d_out;                   /* [T, B, 1024] */

    cudaFuncSetAttribute(darts_mma, cudaFuncAttributeMaxDynamicSharedMemorySize, SMEMT);

    prep<<<2816, PTHR>>>(inputs, h0, W0, Ws);
    darts_mma<<<GBLK, NTHR, SMEMT>>>(inputs, h0, out);
}

// round 13
// speedup vs baseline: 1.0741x; 1.0741x over previous
#include <cuda_runtime.h>
#include <cuda_bf16.h>
#include <math.h>
#include <stdint.h>

typedef uint32_t u32;
typedef unsigned long long u64;

#define TT 256
#define BB 256
#define HH 1024
#define N2 2048
#define BMH (BB*HH)
#define NTHR 256                 /* 8 warps/CTA (R11 proven core) */
#define PTHR 256
#define GBLK 128
#define CHU 1024                 /* uint4 per 16KB image block */
#define BSMAX 49152              /* chunk buffer stride (T64 size) */
#define SMEMT (3*BSMAX)          /* 3-stage pipeline */
#define SWZ(o) ((o) ^ (((o) >> 3) & 0x70))

/* fp32 states s0..s8 */
__device__ float g_S[9][BMH];
/* bf16 hi/lo swizzled images */
__device__ uint4 g_Sih[288 * CHU], g_Sil[288 * CHU];
__device__ uint4 g_Xh[32 * CHU],  g_Xl[32 * CHU];
__device__ uint4 g_Hh[32 * CHU],  g_Hl[32 * CHU];
__device__ uint4 g_W0h[512 * CHU], g_W0l[512 * CHU];
__device__ uint4 g_Wsh[2048 * CHU], g_Wsl[2048 * CHU];
__device__ u64 g_bar;

/* ---------------- helpers ---------------- */
__device__ __forceinline__ float sigf(float v) { return 1.0f / (1.0f + expf(-v)); }
__device__ __forceinline__ float actf(float v, int a) {
    switch (a) { case 0: return sigf(v); case 1: return fmaxf(v, 0.0f);
                 case 2: return tanhf(v); default: return v; }
}
__device__ __forceinline__ u32 smem_u32(const void* p) {
    u32 a; asm("{ .reg .u64 t; cvta.to.shared.u64 t, %1; cvt.u32.u64 %0, t; }" : "=r"(a) : "l"(p));
    return a;
}
__device__ __forceinline__ void split8(const float* v, uint4& hi, uint4& lo) {
    u32 h[4], l[4];
#pragma unroll
    for (int p = 0; p < 4; p++) {
        __nv_bfloat16 b0 = __float2bfloat16(v[2*p]);
        __nv_bfloat16 b1 = __float2bfloat16(v[2*p+1]);
        __nv_bfloat16 c0 = __float2bfloat16(v[2*p]   - __bfloat162float(b0));
        __nv_bfloat16 c1 = __float2bfloat16(v[2*p+1] - __bfloat162float(b1));
        h[p] = (u32)__bfloat16_as_ushort(b0) | ((u32)__bfloat16_as_ushort(b1) << 16);
        l[p] = (u32)__bfloat16_as_ushort(c0) | ((u32)__bfloat16_as_ushort(c1) << 16);
    }
    hi = make_uint4(h[0], h[1], h[2], h[3]);
    lo = make_uint4(l[0], l[1], l[2], l[3]);
}
__device__ __forceinline__ void split2(float s0, float s1, u32& hi, u32& lo) {
    __nv_bfloat16 b0 = __float2bfloat16(s0), b1 = __float2bfloat16(s1);
    __nv_bfloat16 c0 = __float2bfloat16(s0 - __bfloat162float(b0));
    __nv_bfloat16 c1 = __float2bfloat16(s1 - __bfloat162float(b1));
    hi = (u32)__bfloat16_as_ushort(b0) | ((u32)__bfloat16_as_ushort(b1) << 16);
    lo = (u32)__bfloat16_as_ushort(c0) | ((u32)__bfloat16_as_ushort(c1) << 16);
}

/* ---------------- warp MMA primitives ---------------- */
__device__ __forceinline__ void ldsm4(u32* d, u32 a) {
    asm volatile("ldmatrix.sync.aligned.m8n8.x4.shared.b16 {%0,%1,%2,%3}, [%4];"
        : "=r"(d[0]), "=r"(d[1]), "=r"(d[2]), "=r"(d[3]) : "r"(a));
}
__device__ __forceinline__ void ldsm2(u32* d, u32 a) {
    asm volatile("ldmatrix.sync.aligned.m8n8.x2.shared.b16 {%0,%1}, [%2];"
        : "=r"(d[0]), "=r"(d[1]) : "r"(a));
}
__device__ __forceinline__ void mma16816(float* c, const u32* a, const u32* b) {
    asm volatile("mma.sync.aligned.m16n8k16.row.col.f32.bf16.bf16.f32 "
        "{%0,%1,%2,%3}, {%4,%5,%6,%7}, {%8,%9}, {%0,%1,%2,%3};"
        : "+f"(c[0]), "+f"(c[1]), "+f"(c[2]), "+f"(c[3])
        : "r"(a[0]), "r"(a[1]), "r"(a[2]), "r"(a[3]), "r"(b[0]), "r"(b[1]));
}
#define CPA(dst, src) asm volatile("cp.async.cg.shared.global [%0], [%1], 16;" :: "r"(dst), "l"(src))
#define CPCOMMIT()    asm volatile("cp.async.commit_group;" ::: "memory")
#define CPWAIT1()     asm volatile("cp.async.wait_group 1;" ::: "memory")
#define CPWAIT0()     asm volatile("cp.async.wait_group 0;" ::: "memory")

/* ---------------- grid barrier ---------------- */
__device__ __forceinline__ void gridbar() {
    __threadfence();
    __syncthreads();
    if (threadIdx.x == 0) {
        u64 t = atomicAdd(&g_bar, 1ULL);
        u64 goal = (t / GBLK + 1ULL) * (u64)GBLK;
        u64 v;
        do { asm volatile("ld.acquire.gpu.u64 %0, [%1];" : "=l"(v) : "l"(&g_bar) : "memory"); }
        while (v < goal);
    }
    __syncthreads();
}

/* ---------------- prep: build swizzled bf16 hi/lo images (verified) ---------------- */
__global__ __launch_bounds__(PTHR) void prep(
    const float* __restrict__ inputs, const float* __restrict__ h0,
    const float* __restrict__ W0, const float* __restrict__ Ws)
{
    __shared__ float s[64][129];
    const int b = blockIdx.x, tid = threadIdx.x;

    if (b < 2560) {
        const float* Wsrc; int nt, kc; uint4 *dh, *dl;
        if (b < 512) {
            nt = b >> 5; kc = b & 31; Wsrc = W0;
            dh = g_W0h + (size_t)b * CHU; dl = g_W0l + (size_t)b * CHU;
        } else {
            int b2 = b - 512;
            nt = (b2 >> 4) & 15; kc = b2 & 15;
            Wsrc = Ws + (size_t)(b2 >> 8) * HH * N2;
            dh = g_Wsh + (size_t)b2 * CHU; dl = g_Wsl + (size_t)b2 * CHU;
        }
        for (int i = tid; i < 64 * 128; i += PTHR) {
            int k = i >> 7, r = i & 127;
            int n = (r < 64) ? nt * 64 + r : HH + nt * 64 + (r - 64);
            s[k][r] = Wsrc[(size_t)(kc * 64 + k) * N2 + n];
        }
        __syncthreads();
        for (int uu = tid; uu < 1024; uu += PTHR) {
            int r = uu >> 3, g = uu & 7;
            float v[8];
#pragma unroll
            for (int i = 0; i < 8; i++) v[i] = s[g * 8 + i][r];
            uint4 hi, lo; split8(v, hi, lo);
            u32 off = SWZ((u32)(r * 128 + g * 16));
            dh[off >> 4] = hi; dl[off >> 4] = lo;
        }
    } else {
        int b3 = b - 2560;
        const float* src = (b3 < 128) ? inputs : h0;
        uint4* dh = (b3 < 128) ? g_Xh : g_Hh;
        uint4* dl = (b3 < 128) ? g_Xl : g_Hl;
        int uu = (b3 & 127) * PTHR + tid;
        int g = uu & 7, r = (uu >> 3) & 127, kc = (uu >> 10) & 15, mt = uu >> 14;
        int m = mt * 128 + r, k = kc * 64 + g * 8;
        const float4* p = (const float4*)(src + (size_t)m * HH + k);
        float4 a = p[0], bq = p[1];
        float v[8] = {a.x, a.y, a.z, a.w, bq.x, bq.y, bq.z, bq.w};
        uint4 hi, lo; split8(v, hi, lo);
        u32 off = SWZ((u32)(r * 128 + g * 16));
        size_t blk = (size_t)(mt * 16 + kc) * CHU;
        dh[blk + (off >> 4)] = hi; dl[blk + (off >> 4)] = lo;
    }
}

/* ---------------- fused full-K GEMM tile + DARTS epilogue, 8 warps ----------------
 * MT rows x 64-j block (64 c || 64 h). Warp grid 2(M)x4(N) [T64], 1x8 [T32].
 * 3-stage cp.async pipeline, distance-2 prefetch, ONE __syncthreads per chunk. */
template<int MT>
__device__ __noinline__ void run_tile(
    u32 sbase,
    const uint4* __restrict__ Ah0, const uint4* __restrict__ Al0,
    const uint4* __restrict__ Ah1, const uint4* __restrict__ Al1,
    int n1, int nchunks, int rowoff,
    const uint4* __restrict__ Wh, const uint4* __restrict__ Wl,
    const float* __restrict__ sp, float* __restrict__ Sout,
    uint4* imgH, uint4* imgL, int act, int m0, int j0)
{
    constexpr int WN  = (MT == 64) ? 4 : 8;   /* warps along N */
    constexpr int WM  = 8 / WN;               /* warps along M */
    constexpr int MF  = MT / (16 * WM);       /* 16-row m-frags per warp (=2) */
    constexpr int NFC = 64 / (8 * WN);        /* n8 c-frags per warp (T64:2, T32:1) */
    constexpr int JW  = 64 / WN;
    const int tid = threadIdx.x, lid = tid & 31, wid = tid >> 5;
    const int wm = wid / WN, wn = wid % WN;
    const int ncw = wn * JW;

    float accC[MF][NFC][4], accH[MF][NFC][4];
#pragma unroll
    for (int i = 0; i < MF; i++)
#pragma unroll
        for (int j = 0; j < NFC; j++)
#pragma unroll
            for (int q = 0; q < 4; q++) { accC[i][j][q] = 0.f; accH[i][j][q] = 0.f; }

    const int arl = (lid & 7) + ((lid >> 3) & 1) * 8;
    const u32 aXor = (u32)((lid & 7) << 4);
    const u32 aK = (u32)((lid >> 4) * 16);
    const int lb = lid & 15;
    const u32 bXor = (u32)((lb & 7) << 4);
    const u32 bK = (u32)(((lb >> 3) & 1) * 16);
    const int brl = lb & 7;

    auto issue = [&](int c, int buf) {
        const uint4* Ahc = (c < n1) ? (Ah0 + (size_t)c * CHU) : (Ah1 + (size_t)(c - n1) * CHU);
        const uint4* Alc = (c < n1) ? (Al0 + (size_t)c * CHU) : (Al1 + (size_t)(c - n1) * CHU);
        const uint4* Wch = Wh + (size_t)c * CHU;
        const uint4* Wcl = Wl + (size_t)c * CHU;
        u32 d = sbase + (u32)buf * BSMAX;
        /* A hi + lo: MT*8 uint4 each */
#pragma unroll
        for (int i = 0; i < MT * 8 / NTHR; i++) {
            CPA(d + (u32)(tid + i * NTHR) * 16u, (const void*)(Ahc + rowoff + tid + i * NTHR));
            CPA(d + (u32)MT * 128u + (u32)(tid + i * NTHR) * 16u, (const void*)(Alc + rowoff + tid + i * NTHR));
        }
        u32 wb = d + 2u * (u32)MT * 128u;
#pragma unroll
        for (int i = 0; i < 4; i++) {
            CPA(wb + (u32)(tid + i * NTHR) * 16u, (const void*)(Wch + tid + i * NTHR));
            CPA(wb + 16384u + (u32)(tid + i * NTHR) * 16u, (const void*)(Wcl + tid + i * NTHR));
        }
        CPCOMMIT();
    };

    issue(0, 0);
    if (nchunks > 1) issue(1, 1);
    for (int ci = 0; ci < nchunks; ci++) {
        if (ci < nchunks - 1) { CPWAIT1(); } else { CPWAIT0(); }
        __syncthreads();   /* chunk ci landed for all; all warps done with chunk ci-1 */
        if (ci + 2 < nchunks) issue(ci + 2, (ci + 2) % 3);   /* buffer of ci-1, now free */
        u32 b0 = sbase + (u32)(ci % 3) * BSMAX;
        u32 wB = b0 + 2u * MT * 128;
#pragma unroll
        for (int ks = 0; ks < 4; ks++) {
            u32 ah[MF][4], al[MF][4];
            u32 ka = ((u32)(ks * 32) + aK) ^ aXor;
#pragma unroll
            for (int mf = 0; mf < MF; mf++) {
                u32 ad = b0 + (u32)((wm * (MT / WM) + mf * 16 + arl) * 128) + ka;
                ldsm4(ah[mf], ad);
                ldsm4(al[mf], ad + (u32)MT * 128);
            }
            u32 kb = ((u32)(ks * 32) + bK) ^ bXor;
            u32 bhC[NFC][2], blC[NFC][2], bhH[NFC][2], blH[NFC][2];
#pragma unroll
            for (int nf = 0; nf < NFC; nf++) {
                u32 bc = wB + (u32)((ncw + nf * 8 + brl) * 128) + kb;
                ldsm2(bhC[nf], bc); ldsm2(blC[nf], bc + 16384u);
                u32 bh = wB + (u32)((64 + ncw + nf * 8 + brl) * 128) + kb;
                ldsm2(bhH[nf], bh); ldsm2(blH[nf], bh + 16384u);
            }
#pragma unroll
            for (int mf = 0; mf < MF; mf++)
#pragma unroll
                for (int nf = 0; nf < NFC; nf++) {
                    mma16816(accC[mf][nf], ah[mf], bhC[nf]);
                    mma16816(accC[mf][nf], ah[mf], blC[nf]);
                    mma16816(accC[mf][nf], al[mf], bhC[nf]);
                    mma16816(accH[mf][nf], ah[mf], bhH[nf]);
                    mma16816(accH[mf][nf], ah[mf], blH[nf]);
                    mma16816(accH[mf][nf], al[mf], bhH[nf]);
                }
        }
    }
    __syncthreads();   /* protect smem before next phase's run_tile reuses buffers */

    /* fused epilogue */
#pragma unroll
    for (int mf = 0; mf < MF; mf++)
#pragma unroll
        for (int nf = 0; nf < NFC; nf++) {
            int rb = m0 + wm * (MT / WM) + mf * 16 + (lid >> 2);
            int j = j0 + ncw + nf * 8 + (lid & 3) * 2;
#pragma unroll
            for (int hr = 0; hr < 2; hr++) {
                int r = rb + hr * 8;
                float cv0 = accC[mf][nf][hr * 2 + 0], cv1 = accC[mf][nf][hr * 2 + 1];
                float hv0 = accH[mf][nf][hr * 2 + 0], hv1 = accH[mf][nf][hr * 2 + 1];
                float2 spv = *(const float2*)(sp + (size_t)r * HH + j);
                float s0 = spv.x + sigf(cv0) * (actf(hv0, act) - spv.x);
                float s1 = spv.y + sigf(cv1) * (actf(hv1, act) - spv.y);
                *(float2*)(Sout + (size_t)r * HH + j) = make_float2(s0, s1);
                if (imgH) {
                    u32 hi, lo; split2(s0, s1, hi, lo);
                    u32 off = SWZ((u32)((r & 127) * 128 + (j & 63) * 2));
                    *(u32*)((char*)imgH + off) = hi;
                    *(u32*)((char*)imgL + off) = lo;
                }
            }
        }
}

/* ---------------- persistent kernel ---------------- */
__global__ __launch_bounds__(NTHR, 1) void darts_mma(
    const float* __restrict__ inputs, const float* __restrict__ h0,
    float* __restrict__ out)
{
    extern __shared__ char smem[];
    const u32 sbase = smem_u32(smem);
    const int tid = threadIdx.x, bid = blockIdx.x;

    for (int t = 0; t < TT; t++) {
        const float* hp = t ? (out + (size_t)(t - 1) * BMH) : h0;

        /* Phase A: s0 over concat(x, h_prev), K=2048. 128 T32 tasks, tanh. */
        {
            int m0 = (bid >> 4) * 32, nt = bid & 15, mtb = m0 >> 7, ro = (m0 & 127) * 8;
            run_tile<32>(sbase,
                g_Xh + (size_t)mtb * 16 * CHU, g_Xl + (size_t)mtb * 16 * CHU,
                g_Hh + (size_t)mtb * 16 * CHU, g_Hl + (size_t)mtb * 16 * CHU,
                16, 32, ro,
                g_W0h + (size_t)nt * 32 * CHU, g_W0l + (size_t)nt * 32 * CHU,
                hp, g_S[0],
                g_Sih + ((size_t)mtb * 16 + nt) * CHU,
                g_Sil + ((size_t)mtb * 16 + nt) * CHU, 2, m0, nt * 64);
        }
        gridbar();

        /* Phase B: s1 = f(s0, Ws0, sigmoid). 128 T32 tasks, K=1024. */
        {
            int m0 = (bid >> 4) * 32, nt = bid & 15, mtb = m0 >> 7, ro = (m0 & 127) * 8;
            run_tile<32>(sbase,
                g_Sih + (size_t)mtb * 16 * CHU, g_Sil + (size_t)mtb * 16 * CHU,
                (const uint4*)0, (const uint4*)0, 16, 16, ro,
                g_Wsh + (size_t)nt * 16 * CHU, g_Wsl + (size_t)nt * 16 * CHU,
                g_S[0], g_S[1],
                g_Sih + ((size_t)(32 + mtb * 16 + nt)) * CHU,
                g_Sil + ((size_t)(32 + mtb * 16 + nt)) * CHU, 0, m0, nt * 64);
        }
        gridbar();

        /* Phase C: s2 (bid<64) / s3 (bid>=64) from s1. 128 T64 tasks, relu. */
        {
            int op = bid >> 6, sub = bid & 63;
            int m0 = (sub >> 4) * 64, nt = sub & 15, mtb = m0 >> 7, ro = (m0 & 127) * 8;
            int os = 2 + op;
            run_tile<64>(sbase,
                g_Sih + (size_t)(32 + mtb * 16) * CHU, g_Sil + (size_t)(32 + mtb * 16) * CHU,
                (const uint4*)0, (const uint4*)0, 16, 16, ro,
                g_Wsh + (size_t)((1 + op) * 256 + nt * 16) * CHU,
                g_Wsl + (size_t)((1 + op) * 256 + nt * 16) * CHU,
                g_S[1], g_S[os],
                g_Sih + ((size_t)(os * 32 + mtb * 16 + nt)) * CHU,
                g_Sil + ((size_t)(os * 32 + mtb * 16 + nt)) * CHU, 1, m0, nt * 64);
        }
        gridbar();

        /* Phase D: s5<-s2 / s7<-s3 (T64, tanh), then s4<-s1 (T32, identity). */
        {
            int op = bid >> 6, sub = bid & 63;
            int m0 = (sub >> 4) * 64, nt = sub & 15, mtb = m0 >> 7, ro = (m0 & 127) * 8;
            int is = op ? 3 : 2, os = op ? 7 : 5, wop = op ? 6 : 4;
            uint4* ih = op ? (uint4*)0 : g_Sih + ((size_t)(5 * 32 + mtb * 16 + nt)) * CHU;
            uint4* il = op ? (uint4*)0 : g_Sil + ((size_t)(5 * 32 + mtb * 16 + nt)) * CHU;
            run_tile<64>(sbase,
                g_Sih + (size_t)(is * 32 + mtb * 16) * CHU, g_Sil + (size_t)(is * 32 + mtb * 16) * CHU,
                (const uint4*)0, (const uint4*)0, 16, 16, ro,
                g_Wsh + (size_t)(wop * 256 + nt * 16) * CHU,
                g_Wsl + (size_t)(wop * 256 + nt * 16) * CHU,
                g_S[is], g_S[os], ih, il, 2, m0, nt * 64);

            int m0b = (bid >> 4) * 32, ntb = bid & 15, mtb2 = m0b >> 7, rob = (m0b & 127) * 8;
            run_tile<32>(sbase,
                g_Sih + (size_t)(32 + mtb2 * 16) * CHU, g_Sil + (size_t)(32 + mtb2 * 16) * CHU,
                (const uint4*)0, (const uint4*)0, 16, 16, rob,
                g_Wsh + (size_t)(3 * 256 + ntb * 16) * CHU,
                g_Wsl + (size_t)(3 * 256 + ntb * 16) * CHU,
                g_S[1], g_S[4], (uint4*)0, (uint4*)0, 3, m0b, ntb * 64);
        }
        gridbar();

        /* Phase E: s6<-s5 (sigmoid) / s8<-s5 (relu). 128 T64 tasks. */
        {
            int op = bid >> 6, sub = bid & 63;
            int m0 = (sub >> 4) * 64, nt = sub & 15, mtb = m0 >> 7, ro = (m0 & 127) * 8;
            int os = op ? 8 : 6, wop = op ? 7 : 5, a = op ? 1 : 0;
            run_tile<64>(sbase,
                g_Sih + (size_t)(5 * 32 + mtb * 16) * CHU, g_Sil + (size_t)(5 * 32 + mtb * 16) * CHU,
                (const uint4*)0, (const uint4*)0, 16, 16, ro,
                g_Wsh + (size_t)(wop * 256 + nt * 16) * CHU,
                g_Wsl + (size_t)(wop * 256 + nt * 16) * CHU,
                g_S[5], g_S[os], (uint4*)0, (uint4*)0, a, m0, nt * 64);
        }
        gridbar();

        /* Phase F: out[t] = mean(s1..s8); emit h image; convert x_{t+1} image. */
        {
            float* ot = out + (size_t)t * BMH;
            int uu = bid * NTHR + tid;               /* 32768 tasks of 8 floats */
            int m = uu >> 7, j = (uu & 127) * 8;
            float a[8] = {0.f, 0.f, 0.f, 0.f, 0.f, 0.f, 0.f, 0.f};
#pragma unroll
            for (int s = 1; s < 9; s++) {
                const float4* p = (const float4*)(&g_S[s][(size_t)m * HH + j]);
                float4 v0 = p[0], v1 = p[1];
                a[0] += v0.x; a[1] += v0.y; a[2] += v0.z; a[3] += v0.w;
                a[4] += v1.x; a[5] += v1.y; a[6] += v1.z; a[7] += v1.w;
            }
#pragma unroll
            for (int q = 0; q < 8; q++) a[q] *= 0.125f;
            float4* q4 = (float4*)(ot + (size_t)m * HH + j);
            q4[0] = make_float4(a[0], a[1], a[2], a[3]);
            q4[1] = make_float4(a[4], a[5], a[6], a[7]);
            {
                uint4 hi, lo; split8(a, hi, lo);
                u32 off = SWZ((u32)((m & 127) * 128 + (j & 63) * 2));
                size_t blk = ((size_t)(m >> 7) * 16 + (j >> 6)) * CHU;
                g_Hh[blk + (off >> 4)] = hi; g_Hl[blk + (off >> 4)] = lo;
            }
            if (t + 1 < TT) {
                const float4* p = (const float4*)(inputs + (size_t)(t + 1) * BMH + (size_t)m * HH + j);
                float4 v0 = p[0], v1 = p[1];
                float v[8] = {v0.x, v0.y, v0.z, v0.w, v1.x, v1.y, v1.z, v1.w};
                uint4 hi, lo; split8(v, hi, lo);
                u32 off = SWZ((u32)((m & 127) * 128 + (j & 63) * 2));
                size_t blk = ((size_t)(m >> 7) * 16 + (j >> 6)) * CHU;
                g_Xh[blk + (off >> 4)] = hi; g_Xl[blk + (off >> 4)] = lo;
            }
        }
        gridbar();
    }
}

extern "C" void kernel_launch(void* const* d_in, const int* in_sizes, int n_in,
                              void* d_out, int out_size)
{
    const float* inputs = (const float*)d_in[0];  /* [T, B, 1024] */
    const float* h0     = (const float*)d_in[1];  /* [B, 1024]    */
    const float* W0     = (const float*)d_in[2];  /* [2048, 2048] */
    const float* Ws     = (const float*)d_in[3];  /* [8, 1024, 2048] */
    float* out = (float*)d_out;                   /* [T, B, 1024] */

    cudaFuncSetAttribute(darts_mma, cudaFuncAttributeMaxDynamicSharedMemorySize, SMEMT);

    prep<<<2816, PTHR>>>(inputs, h0, W0, Ws);
    darts_mma<<<GBLK, NTHR, SMEMT>>>(inputs, h0, out);
}

// round 16
// speedup vs baseline: 1.3607x; 1.2668x over previous
#include <cuda_runtime.h>
#include <cuda_fp16.h>
#include <math.h>
#include <stdint.h>

typedef uint32_t u32;
typedef unsigned long long u64;

#define TT 256
#define BB 256
#define HH 1024
#define N2 2048
#define BMH (BB*HH)
#define NTHR 256                 /* 8 warps/CTA */
#define PTHR 256
#define GBLK 128
#define CHU 1024                 /* uint4 per 16KB image block */
#define BSMAX 32768              /* chunk buffer stride (T64: 8+8+16 KB) */
#define SMEMT (4*BSMAX)          /* 4-stage pipeline */
#define SWZ(o) ((o) ^ (((o) >> 3) & 0x70))

/* fp32 states s0..s8 */
__device__ float g_S[9][BMH];
/* fp16 swizzled images. A-side: hi+lo pairs. W-side: single fp16 (truncated). */
__device__ uint4 g_Sih[288 * CHU], g_Sil[288 * CHU];
__device__ uint4 g_Xh[32 * CHU],  g_Xl[32 * CHU];
__device__ uint4 g_Hh[32 * CHU],  g_Hl[32 * CHU];
__device__ uint4 g_W0f[512 * CHU];          /* W0: [nt*32+kc] */
__device__ uint4 g_Wsf[2048 * CHU];         /* Ws: [op*256+nt*16+kc] */
__device__ u64 g_bar;

/* ---------------- helpers ---------------- */
__device__ __forceinline__ float sigf(float v) { return 1.0f / (1.0f + expf(-v)); }
__device__ __forceinline__ float actf(float v, int a) {
    switch (a) { case 0: return sigf(v); case 1: return fmaxf(v, 0.0f);
                 case 2: return tanhf(v); default: return v; }
}
__device__ __forceinline__ u32 smem_u32(const void* p) {
    u32 a; asm("{ .reg .u64 t; cvta.to.shared.u64 t, %1; cvt.u32.u64 %0, t; }" : "=r"(a) : "l"(p));
    return a;
}
/* 8 fp32 -> 8 fp16 (hi) + 8 fp16 residual (lo), each packed as one uint4 */
__device__ __forceinline__ void split8h(const float* v, uint4& hi, uint4& lo) {
    u32 h[4], l[4];
#pragma unroll
    for (int p = 0; p < 4; p++) {
        __half b0 = __float2half_rn(v[2*p]);
        __half b1 = __float2half_rn(v[2*p+1]);
        __half c0 = __float2half_rn(v[2*p]   - __half2float(b0));
        __half c1 = __float2half_rn(v[2*p+1] - __half2float(b1));
        h[p] = (u32)__half_as_ushort(b0) | ((u32)__half_as_ushort(b1) << 16);
        l[p] = (u32)__half_as_ushort(c0) | ((u32)__half_as_ushort(c1) << 16);
    }
    hi = make_uint4(h[0], h[1], h[2], h[3]);
    lo = make_uint4(l[0], l[1], l[2], l[3]);
}
/* 8 fp32 -> 8 fp16 packed uint4 (truncate, for W) */
__device__ __forceinline__ uint4 pack8h(const float* v) {
    u32 h[4];
#pragma unroll
    for (int p = 0; p < 4; p++) {
        h[p] = (u32)__half_as_ushort(__float2half_rn(v[2*p]))
             | ((u32)__half_as_ushort(__float2half_rn(v[2*p+1])) << 16);
    }
    return make_uint4(h[0], h[1], h[2], h[3]);
}
__device__ __forceinline__ void split2h(float s0, float s1, u32& hi, u32& lo) {
    __half b0 = __float2half_rn(s0), b1 = __float2half_rn(s1);
    __half c0 = __float2half_rn(s0 - __half2float(b0));
    __half c1 = __float2half_rn(s1 - __half2float(b1));
    hi = (u32)__half_as_ushort(b0) | ((u32)__half_as_ushort(b1) << 16);
    lo = (u32)__half_as_ushort(c0) | ((u32)__half_as_ushort(c1) << 16);
}

/* ---------------- warp MMA primitives ---------------- */
__device__ __forceinline__ void ldsm4(u32* d, u32 a) {
    asm volatile("ldmatrix.sync.aligned.m8n8.x4.shared.b16 {%0,%1,%2,%3}, [%4];"
        : "=r"(d[0]), "=r"(d[1]), "=r"(d[2]), "=r"(d[3]) : "r"(a));
}
__device__ __forceinline__ void ldsm2(u32* d, u32 a) {
    asm volatile("ldmatrix.sync.aligned.m8n8.x2.shared.b16 {%0,%1}, [%2];"
        : "=r"(d[0]), "=r"(d[1]) : "r"(a));
}
__device__ __forceinline__ void mma16816(float* c, const u32* a, const u32* b) {
    asm volatile("mma.sync.aligned.m16n8k16.row.col.f32.f16.f16.f32 "
        "{%0,%1,%2,%3}, {%4,%5,%6,%7}, {%8,%9}, {%0,%1,%2,%3};"
        : "+f"(c[0]), "+f"(c[1]), "+f"(c[2]), "+f"(c[3])
        : "r"(a[0]), "r"(a[1]), "r"(a[2]), "r"(a[3]), "r"(b[0]), "r"(b[1]));
}
#define CPA(dst, src) asm volatile("cp.async.cg.shared.global [%0], [%1], 16;" :: "r"(dst), "l"(src))
#define CPCOMMIT()    asm volatile("cp.async.commit_group;" ::: "memory")
#define CPWAIT2()     asm volatile("cp.async.wait_group 2;" ::: "memory")
#define CPWAIT1()     asm volatile("cp.async.wait_group 1;" ::: "memory")
#define CPWAIT0()     asm volatile("cp.async.wait_group 0;" ::: "memory")

/* ---------------- grid barrier ---------------- */
__device__ __forceinline__ void gridbar() {
    __threadfence();
    __syncthreads();
    if (threadIdx.x == 0) {
        u64 t = atomicAdd(&g_bar, 1ULL);
        u64 goal = (t / GBLK + 1ULL) * (u64)GBLK;
        u64 v;
        do { asm volatile("ld.acquire.gpu.u64 %0, [%1];" : "=l"(v) : "l"(&g_bar) : "memory"); }
        while (v < goal);
    }
    __syncthreads();
}

/* ---------------- prep: build swizzled fp16 images ---------------- */
__global__ __launch_bounds__(PTHR) void prep(
    const float* __restrict__ inputs, const float* __restrict__ h0,
    const float* __restrict__ W0, const float* __restrict__ Ws)
{
    __shared__ float s[64][129];
    const int b = blockIdx.x, tid = threadIdx.x;

    if (b < 2560) {
        /* weight block: 128 rows (64 c + 64 h) x 64 k, single fp16, swizzled */
        const float* Wsrc; int nt, kc; uint4* df;
        if (b < 512) {
            nt = b >> 5; kc = b & 31; Wsrc = W0;
            df = g_W0f + (size_t)b * CHU;
        } else {
            int b2 = b - 512;
            nt = (b2 >> 4) & 15; kc = b2 & 15;
            Wsrc = Ws + (size_t)(b2 >> 8) * HH * N2;
            df = g_Wsf + (size_t)b2 * CHU;
        }
        for (int i = tid; i < 64 * 128; i += PTHR) {
            int k = i >> 7, r = i & 127;
            int n = (r < 64) ? nt * 64 + r : HH + nt * 64 + (r - 64);
            s[k][r] = Wsrc[(size_t)(kc * 64 + k) * N2 + n];
        }
        __syncthreads();
        for (int uu = tid; uu < 1024; uu += PTHR) {
            int r = uu >> 3, g = uu & 7;
            float v[8];
#pragma unroll
            for (int i = 0; i < 8; i++) v[i] = s[g * 8 + i][r];
            u32 off = SWZ((u32)(r * 128 + g * 16));
            df[off >> 4] = pack8h(v);
        }
    } else {
        /* x0 / h0 hi+lo image conversion */
        int b3 = b - 2560;
        const float* src = (b3 < 128) ? inputs : h0;
        uint4* dh = (b3 < 128) ? g_Xh : g_Hh;
        uint4* dl = (b3 < 128) ? g_Xl : g_Hl;
        int uu = (b3 & 127) * PTHR + tid;
        int g = uu & 7, r = (uu >> 3) & 127, kc = (uu >> 10) & 15, mt = uu >> 14;
        int m = mt * 128 + r, k = kc * 64 + g * 8;
        const float4* p = (const float4*)(src + (size_t)m * HH + k);
        float4 a = p[0], bq = p[1];
        float v[8] = {a.x, a.y, a.z, a.w, bq.x, bq.y, bq.z, bq.w};
        uint4 hi, lo; split8h(v, hi, lo);
        u32 off = SWZ((u32)(r * 128 + g * 16));
        size_t blk = (size_t)(mt * 16 + kc) * CHU;
        dh[blk + (off >> 4)] = hi; dl[blk + (off >> 4)] = lo;
    }
}

/* ---------------- fused full-K GEMM tile + DARTS epilogue, 8 warps ----------------
 * MT rows x 64-j block (64 c || 64 h). A = fp16 hi+lo (2-pass compensation),
 * W = fp16 single. D = Ah*W + Al*W. 4-stage cp.async pipeline, distance-3. */
template<int MT>
__device__ __noinline__ void run_tile(
    u32 sbase,
    const uint4* __restrict__ Ah0, const uint4* __restrict__ Al0,
    const uint4* __restrict__ Ah1, const uint4* __restrict__ Al1,
    int n1, int nchunks, int rowoff,
    const uint4* __restrict__ Wf,
    const float* __restrict__ sp, float* __restrict__ Sout,
    uint4* imgH, uint4* imgL, int act, int m0, int j0)
{
    constexpr int WN  = (MT == 64) ? 4 : 8;   /* warps along N */
    constexpr int WM  = 8 / WN;
    constexpr int MF  = MT / (16 * WM);       /* =2 */
    constexpr int NFC = 64 / (8 * WN);        /* T64:2, T32:1 */
    constexpr int JW  = 64 / WN;
    const int tid = threadIdx.x, lid = tid & 31, wid = tid >> 5;
    const int wm = wid / WN, wn = wid % WN;
    const int ncw = wn * JW;

    float accC[MF][NFC][4], accH[MF][NFC][4];
#pragma unroll
    for (int i = 0; i < MF; i++)
#pragma unroll
        for (int j = 0; j < NFC; j++)
#pragma unroll
            for (int q = 0; q < 4; q++) { accC[i][j][q] = 0.f; accH[i][j][q] = 0.f; }

    const int arl = (lid & 7) + ((lid >> 3) & 1) * 8;
    const u32 aXor = (u32)((lid & 7) << 4);
    const u32 aK = (u32)((lid >> 4) * 16);
    const int lb = lid & 15;
    const u32 bXor = (u32)((lb & 7) << 4);
    const u32 bK = (u32)(((lb >> 3) & 1) * 16);
    const int brl = lb & 7;

    auto issue = [&](int c, int buf) {
        const uint4* Ahc = (c < n1) ? (Ah0 + (size_t)c * CHU) : (Ah1 + (size_t)(c - n1) * CHU);
        const uint4* Alc = (c < n1) ? (Al0 + (size_t)c * CHU) : (Al1 + (size_t)(c - n1) * CHU);
        const uint4* Wc = Wf + (size_t)c * CHU;
        u32 d = sbase + (u32)buf * BSMAX;
        /* A hi + lo: MT*8 uint4 each */
#pragma unroll
        for (int i = 0; i < MT * 8 / NTHR; i++) {
            CPA(d + (u32)(tid + i * NTHR) * 16u, (const void*)(Ahc + rowoff + tid + i * NTHR));
            CPA(d + (u32)MT * 128u + (u32)(tid + i * NTHR) * 16u, (const void*)(Alc + rowoff + tid + i * NTHR));
        }
        u32 wb = d + 2u * (u32)MT * 128u;
#pragma unroll
        for (int i = 0; i < 4; i++)
            CPA(wb + (u32)(tid + i * NTHR) * 16u, (const void*)(Wc + tid + i * NTHR));
        CPCOMMIT();
    };

    issue(0, 0);
    if (nchunks > 1) issue(1, 1);
    if (nchunks > 2) issue(2, 2);
    for (int ci = 0; ci < nchunks; ci++) {
        if (ci + 2 < nchunks) { CPWAIT2(); }
        else if (ci + 1 < nchunks) { CPWAIT1(); }
        else { CPWAIT0(); }
        __syncthreads();   /* chunk ci landed; all warps done with chunk ci-1 */
        if (ci + 3 < nchunks) issue(ci + 3, (ci + 3) & 3);
        u32 b0 = sbase + (u32)(ci & 3) * BSMAX;
        u32 wB = b0 + 2u * MT * 128;
#pragma unroll
        for (int ks = 0; ks < 4; ks++) {
            u32 ah[MF][4], al[MF][4];
            u32 ka = ((u32)(ks * 32) + aK) ^ aXor;
#pragma unroll
            for (int mf = 0; mf < MF; mf++) {
                u32 ad = b0 + (u32)((wm * (MT / WM) + mf * 16 + arl) * 128) + ka;
                ldsm4(ah[mf], ad);
                ldsm4(al[mf], ad + (u32)MT * 128);
            }
            u32 kb = ((u32)(ks * 32) + bK) ^ bXor;
            u32 wCf[NFC][2], wHf[NFC][2];
#pragma unroll
            for (int nf = 0; nf < NFC; nf++) {
                ldsm2(wCf[nf], wB + (u32)((ncw + nf * 8 + brl) * 128) + kb);
                ldsm2(wHf[nf], wB + (u32)((64 + ncw + nf * 8 + brl) * 128) + kb);
            }
#pragma unroll
            for (int mf = 0; mf < MF; mf++)
#pragma unroll
                for (int nf = 0; nf < NFC; nf++) {
                    mma16816(accC[mf][nf], ah[mf], wCf[nf]);
                    mma16816(accC[mf][nf], al[mf], wCf[nf]);
                    mma16816(accH[mf][nf], ah[mf], wHf[nf]);
                    mma16816(accH[mf][nf], al[mf], wHf[nf]);
                }
        }
    }
    __syncthreads();   /* protect smem before next phase reuses buffers */

    /* fused epilogue */
#pragma unroll
    for (int mf = 0; mf < MF; mf++)
#pragma unroll
        for (int nf = 0; nf < NFC; nf++) {
            int rb = m0 + wm * (MT / WM) + mf * 16 + (lid >> 2);
            int j = j0 + ncw + nf * 8 + (lid & 3) * 2;
#pragma unroll
            for (int hr = 0; hr < 2; hr++) {
                int r = rb + hr * 8;
                float cv0 = accC[mf][nf][hr * 2 + 0], cv1 = accC[mf][nf][hr * 2 + 1];
                float hv0 = accH[mf][nf][hr * 2 + 0], hv1 = accH[mf][nf][hr * 2 + 1];
                float2 spv = *(const float2*)(sp + (size_t)r * HH + j);
                float s0 = spv.x + sigf(cv0) * (actf(hv0, act) - spv.x);
                float s1 = spv.y + sigf(cv1) * (actf(hv1, act) - spv.y);
                *(float2*)(Sout + (size_t)r * HH + j) = make_float2(s0, s1);
                if (imgH) {
                    u32 hi, lo; split2h(s0, s1, hi, lo);
                    u32 off = SWZ((u32)((r & 127) * 128 + (j & 63) * 2));
                    *(u32*)((char*)imgH + off) = hi;
                    *(u32*)((char*)imgL + off) = lo;
                }
            }
        }
}

/* ---------------- persistent kernel ---------------- */
__global__ __launch_bounds__(NTHR, 1) void darts_mma(
    const float* __restrict__ inputs, const float* __restrict__ h0,
    float* __restrict__ out)
{
    extern __shared__ char smem[];
    const u32 sbase = smem_u32(smem);
    const int tid = threadIdx.x, bid = blockIdx.x;

    for (int t = 0; t < TT; t++) {
        const float* hp = t ? (out + (size_t)(t - 1) * BMH) : h0;

        /* Phase A: s0 over concat(x, h_prev), K=2048. 128 T32 tasks, tanh. */
        {
            int m0 = (bid >> 4) * 32, nt = bid & 15, mtb = m0 >> 7, ro = (m0 & 127) * 8;
            run_tile<32>(sbase,
                g_Xh + (size_t)mtb * 16 * CHU, g_Xl + (size_t)mtb * 16 * CHU,
                g_Hh + (size_t)mtb * 16 * CHU, g_Hl + (size_t)mtb * 16 * CHU,
                16, 32, ro,
                g_W0f + (size_t)nt * 32 * CHU,
                hp, g_S[0],
                g_Sih + ((size_t)mtb * 16 + nt) * CHU,
                g_Sil + ((size_t)mtb * 16 + nt) * CHU, 2, m0, nt * 64);
        }
        gridbar();

        /* Phase B: s1 = f(s0, Ws0, sigmoid). 128 T32 tasks, K=1024. */
        {
            int m0 = (bid >> 4) * 32, nt = bid & 15, mtb = m0 >> 7, ro = (m0 & 127) * 8;
            run_tile<32>(sbase,
                g_Sih + (size_t)mtb * 16 * CHU, g_Sil + (size_t)mtb * 16 * CHU,
                (const uint4*)0, (const uint4*)0, 16, 16, ro,
                g_Wsf + (size_t)nt * 16 * CHU,
                g_S[0], g_S[1],
                g_Sih + ((size_t)(32 + mtb * 16 + nt)) * CHU,
                g_Sil + ((size_t)(32 + mtb * 16 + nt)) * CHU, 0, m0, nt * 64);
        }
        gridbar();

        /* Phase C: s2 (bid<64) / s3 (bid>=64) from s1. 128 T64 tasks, relu. */
        {
            int op = bid >> 6, sub = bid & 63;
            int m0 = (sub >> 4) * 64, nt = sub & 15, mtb = m0 >> 7, ro = (m0 & 127) * 8;
            int os = 2 + op;
            run_tile<64>(sbase,
                g_Sih + (size_t)(32 + mtb * 16) * CHU, g_Sil + (size_t)(32 + mtb * 16) * CHU,
                (const uint4*)0, (const uint4*)0, 16, 16, ro,
                g_Wsf + (size_t)((1 + op) * 256 + nt * 16) * CHU,
                g_S[1], g_S[os],
                g_Sih + ((size_t)(os * 32 + mtb * 16 + nt)) * CHU,
                g_Sil + ((size_t)(os * 32 + mtb * 16 + nt)) * CHU, 1, m0, nt * 64);
        }
        gridbar();

        /* Phase D: s5<-s2 / s7<-s3 (T64, tanh), then s4<-s1 (T32, identity). */
        {
            int op = bid >> 6, sub = bid & 63;
            int m0 = (sub >> 4) * 64, nt = sub & 15, mtb = m0 >> 7, ro = (m0 & 127) * 8;
            int is = op ? 3 : 2, os = op ? 7 : 5, wop = op ? 6 : 4;
            uint4* ih = op ? (uint4*)0 : g_Sih + ((size_t)(5 * 32 + mtb * 16 + nt)) * CHU;
            uint4* il = op ? (uint4*)0 : g_Sil + ((size_t)(5 * 32 + mtb * 16 + nt)) * CHU;
            run_tile<64>(sbase,
                g_Sih + (size_t)(is * 32 + mtb * 16) * CHU, g_Sil + (size_t)(is * 32 + mtb * 16) * CHU,
                (const uint4*)0, (const uint4*)0, 16, 16, ro,
                g_Wsf + (size_t)(wop * 256 + nt * 16) * CHU,
                g_S[is], g_S[os], ih, il, 2, m0, nt * 64);

            int m0b = (bid >> 4) * 32, ntb = bid & 15, mtb2 = m0b >> 7, rob = (m0b & 127) * 8;
            run_tile<32>(sbase,
                g_Sih + (size_t)(32 + mtb2 * 16) * CHU, g_Sil + (size_t)(32 + mtb2 * 16) * CHU,
                (const uint4*)0, (const uint4*)0, 16, 16, rob,
                g_Wsf + (size_t)(3 * 256 + ntb * 16) * CHU,
                g_S[1], g_S[4], (uint4*)0, (uint4*)0, 3, m0b, ntb * 64);
        }
        gridbar();

        /* Phase E: s6<-s5 (sigmoid) / s8<-s5 (relu). 128 T64 tasks. */
        {
            int op = bid >> 6, sub = bid & 63;
            int m0 = (sub >> 4) * 64, nt = sub & 15, mtb = m0 >> 7, ro = (m0 & 127) * 8;
            int os = op ? 8 : 6, wop = op ? 7 : 5, a = op ? 1 : 0;
            run_tile<64>(sbase,
                g_Sih + (size_t)(5 * 32 + mtb * 16) * CHU, g_Sil + (size_t)(5 * 32 + mtb * 16) * CHU,
                (const uint4*)0, (const uint4*)0, 16, 16, ro,
                g_Wsf + (size_t)(wop * 256 + nt * 16) * CHU,
                g_S[5], g_S[os], (uint4*)0, (uint4*)0, a, m0, nt * 64);
        }
        gridbar();

        /* Phase F: out[t] = mean(s1..s8); emit h image; convert x_{t+1} image. */
        {
            float* ot = out + (size_t)t * BMH;
            int uu = bid * NTHR + tid;               /* 32768 tasks of 8 floats */
            int m = uu >> 7, j = (uu & 127) * 8;
            float a[8] = {0.f, 0.f, 0.f, 0.f, 0.f, 0.f, 0.f, 0.f};
#pragma unroll
            for (int s = 1; s < 9; s++) {
                const float4* p = (const float4*)(&g_S[s][(size_t)m * HH + j]);
                float4 v0 = p[0], v1 = p[1];
                a[0] += v0.x; a[1] += v0.y; a[2] += v0.z; a[3] += v0.w;
                a[4] += v1.x; a[5] += v1.y; a[6] += v1.z; a[7] += v1.w;
            }
#pragma unroll
            for (int q = 0; q < 8; q++) a[q] *= 0.125f;
            float4* q4 = (float4*)(ot + (size_t)m * HH + j);
            q4[0] = make_float4(a[0], a[1], a[2], a[3]);
            q4[1] = make_float4(a[4], a[5], a[6], a[7]);
            {
                uint4 hi, lo; split8h(a, hi, lo);
                u32 off = SWZ((u32)((m & 127) * 128 + (j & 63) * 2));
                size_t blk = ((size_t)(m >> 7) * 16 + (j >> 6)) * CHU;
                g_Hh[blk + (off >> 4)] = hi; g_Hl[blk + (off >> 4)] = lo;
            }
            if (t + 1 < TT) {
                const float4* p = (const float4*)(inputs + (size_t)(t + 1) * BMH + (size_t)m * HH + j);
                float4 v0 = p[0], v1 = p[1];
                float v[8] = {v0.x, v0.y, v0.z, v0.w, v1.x, v1.y, v1.z, v1.w};
                uint4 hi, lo; split8h(v, hi, lo);
                u32 off = SWZ((u32)((m & 127) * 128 + (j & 63) * 2));
                size_t blk = ((size_t)(m >> 7) * 16 + (j >> 6)) * CHU;
                g_Xh[blk + (off >> 4)] = hi; g_Xl[blk + (off >> 4)] = lo;
            }
        }
        gridbar();
    }
}

extern "C" void kernel_launch(void* const* d_in, const int* in_sizes, int n_in,
                              void* d_out, int out_size)
{
    const float* inputs = (const float*)d_in[0];  /* [T, B, 1024] */
    const float* h0     = (const float*)d_in[1];  /* [B, 1024]    */
    const float* W0     = (const float*)d_in[2];  /* [2048, 2048] */
    const float* Ws     = (const float*)d_in[3];  /* [8, 1024, 2048] */
    float* out = (float*)d_out;                   /* [T, B, 1024] */

    cudaFuncSetAttribute(darts_mma, cudaFuncAttributeMaxDynamicSharedMemorySize, SMEMT);

    prep<<<2816, PTHR>>>(inputs, h0, W0, Ws);
    darts_mma<<<GBLK, NTHR, SMEMT>>>(inputs, h0, out);
}

// round 17
// speedup vs baseline: 1.6847x; 1.2382x over previous
#include <cuda_runtime.h>
#include <cuda_fp16.h>
#include <math.h>
#include <stdint.h>

typedef uint32_t u32;
typedef unsigned long long u64;

#define TT 256
#define BB 256
#define HH 1024
#define N2 2048
#define BMH (BB*HH)
#define NTHR 256                 /* 8 warps/CTA */
#define PTHR 256
#define GBLK 256                 /* 2 CTAs/SM target */
#define CHU 1024                 /* uint4 per 16KB image block */
#define BSMAX 20480              /* T32 single-pass chunk: A 4KB + W 16KB */
#define SMEMT (4*BSMAX)          /* 4-stage pipeline = 80KB */
#define SWZ(o) ((o) ^ (((o) >> 3) & 0x70))

/* fp32 states s0..s8 */
__device__ float g_S[9][BMH];
/* fp16 swizzled images (hi only — single-pass) */
__device__ uint4 g_Sih[288 * CHU];
__device__ uint4 g_Xh[32 * CHU];
__device__ uint4 g_Hh[32 * CHU];
__device__ uint4 g_W0f[512 * CHU];          /* W0: [nt*32+kc] */
__device__ uint4 g_Wsf[2048 * CHU];         /* Ws: [op*256+nt*16+kc] */
__device__ u64 g_bar;

/* ---------------- helpers ---------------- */
__device__ __forceinline__ float sigf(float v) { return 1.0f / (1.0f + expf(-v)); }
__device__ __forceinline__ float actf(float v, int a) {
    switch (a) { case 0: return sigf(v); case 1: return fmaxf(v, 0.0f);
                 case 2: return tanhf(v); default: return v; }
}
__device__ __forceinline__ u32 smem_u32(const void* p) {
    u32 a; asm("{ .reg .u64 t; cvta.to.shared.u64 t, %1; cvt.u32.u64 %0, t; }" : "=r"(a) : "l"(p));
    return a;
}
/* 8 fp32 -> 8 fp16 packed uint4 */
__device__ __forceinline__ uint4 pack8h(const float* v) {
    u32 h[4];
#pragma unroll
    for (int p = 0; p < 4; p++) {
        h[p] = (u32)__half_as_ushort(__float2half_rn(v[2*p]))
             | ((u32)__half_as_ushort(__float2half_rn(v[2*p+1])) << 16);
    }
    return make_uint4(h[0], h[1], h[2], h[3]);
}
__device__ __forceinline__ u32 pack2h(float s0, float s1) {
    return (u32)__half_as_ushort(__float2half_rn(s0))
         | ((u32)__half_as_ushort(__float2half_rn(s1)) << 16);
}

/* ---------------- warp MMA primitives ---------------- */
__device__ __forceinline__ void ldsm4(u32* d, u32 a) {
    asm volatile("ldmatrix.sync.aligned.m8n8.x4.shared.b16 {%0,%1,%2,%3}, [%4];"
        : "=r"(d[0]), "=r"(d[1]), "=r"(d[2]), "=r"(d[3]) : "r"(a));
}
__device__ __forceinline__ void ldsm2(u32* d, u32 a) {
    asm volatile("ldmatrix.sync.aligned.m8n8.x2.shared.b16 {%0,%1}, [%2];"
        : "=r"(d[0]), "=r"(d[1]) : "r"(a));
}
__device__ __forceinline__ void mma16816(float* c, const u32* a, const u32* b) {
    asm volatile("mma.sync.aligned.m16n8k16.row.col.f32.f16.f16.f32 "
        "{%0,%1,%2,%3}, {%4,%5,%6,%7}, {%8,%9}, {%0,%1,%2,%3};"
        : "+f"(c[0]), "+f"(c[1]), "+f"(c[2]), "+f"(c[3])
        : "r"(a[0]), "r"(a[1]), "r"(a[2]), "r"(a[3]), "r"(b[0]), "r"(b[1]));
}
#define CPA(dst, src) asm volatile("cp.async.cg.shared.global [%0], [%1], 16;" :: "r"(dst), "l"(src))
#define CPCOMMIT()    asm volatile("cp.async.commit_group;" ::: "memory")
#define CPWAIT2()     asm volatile("cp.async.wait_group 2;" ::: "memory")
#define CPWAIT1()     asm volatile("cp.async.wait_group 1;" ::: "memory")
#define CPWAIT0()     asm volatile("cp.async.wait_group 0;" ::: "memory")

/* ---------------- grid barrier (monotonic, replay-safe) ---------------- */
__device__ __forceinline__ void gridbar() {
    __threadfence();
    __syncthreads();
    if (threadIdx.x == 0) {
        u64 t = atomicAdd(&g_bar, 1ULL);
        u64 goal = (t / GBLK + 1ULL) * (u64)GBLK;
        u64 v;
        do { asm volatile("ld.acquire.gpu.u64 %0, [%1];" : "=l"(v) : "l"(&g_bar) : "memory"); }
        while (v < goal);
    }
    __syncthreads();
}

/* ---------------- prep: build swizzled fp16 images ---------------- */
__global__ __launch_bounds__(PTHR) void prep(
    const float* __restrict__ inputs, const float* __restrict__ h0,
    const float* __restrict__ W0, const float* __restrict__ Ws)
{
    __shared__ float s[64][129];
    const int b = blockIdx.x, tid = threadIdx.x;

    if (b < 2560) {
        /* weight block: 128 rows (64 c + 64 h) x 64 k, fp16, swizzled */
        const float* Wsrc; int nt, kc; uint4* df;
        if (b < 512) {
            nt = b >> 5; kc = b & 31; Wsrc = W0;
            df = g_W0f + (size_t)b * CHU;
        } else {
            int b2 = b - 512;
            nt = (b2 >> 4) & 15; kc = b2 & 15;
            Wsrc = Ws + (size_t)(b2 >> 8) * HH * N2;
            df = g_Wsf + (size_t)b2 * CHU;
        }
        for (int i = tid; i < 64 * 128; i += PTHR) {
            int k = i >> 7, r = i & 127;
            int n = (r < 64) ? nt * 64 + r : HH + nt * 64 + (r - 64);
            s[k][r] = Wsrc[(size_t)(kc * 64 + k) * N2 + n];
        }
        __syncthreads();
        for (int uu = tid; uu < 1024; uu += PTHR) {
            int r = uu >> 3, g = uu & 7;
            float v[8];
#pragma unroll
            for (int i = 0; i < 8; i++) v[i] = s[g * 8 + i][r];
            u32 off = SWZ((u32)(r * 128 + g * 16));
            df[off >> 4] = pack8h(v);
        }
    } else {
        /* x0 / h0 image conversion (hi only) */
        int b3 = b - 2560;
        const float* src = (b3 < 128) ? inputs : h0;
        uint4* dh = (b3 < 128) ? g_Xh : g_Hh;
        int uu = (b3 & 127) * PTHR + tid;
        int g = uu & 7, r = (uu >> 3) & 127, kc = (uu >> 10) & 15, mt = uu >> 14;
        int m = mt * 128 + r, k = kc * 64 + g * 8;
        const float4* p = (const float4*)(src + (size_t)m * HH + k);
        float4 a = p[0], bq = p[1];
        float v[8] = {a.x, a.y, a.z, a.w, bq.x, bq.y, bq.z, bq.w};
        u32 off = SWZ((u32)(r * 128 + g * 16));
        size_t blk = (size_t)(mt * 16 + kc) * CHU;
        dh[blk + (off >> 4)] = pack8h(v);
    }
}

/* ---------------- fused full-K T32 GEMM tile + DARTS epilogue, 8 warps ----------------
 * 32 rows x 64-j block (64 c || 64 h). A = fp16 (single pass), W = fp16.
 * Warp grid 1(M)x8(N); each warp: 2 m-frags x 1 n8-frag.
 * 4-stage cp.async pipeline, distance-3 prefetch, one __syncthreads per chunk. */
__device__ __noinline__ void run_tile(
    u32 sbase,
    const uint4* __restrict__ Ah0, const uint4* __restrict__ Ah1,
    int n1, int nchunks, int rowoff,
    const uint4* __restrict__ Wf,
    const float* __restrict__ sp, float* __restrict__ Sout,
    uint4* imgH, int act, int m0, int j0)
{
    const int tid = threadIdx.x, lid = tid & 31, wid = tid >> 5;
    const int ncw = wid * 8;    /* warp's j-offset within 64 */

    float accC[2][4], accH[2][4];
#pragma unroll
    for (int i = 0; i < 2; i++)
#pragma unroll
        for (int q = 0; q < 4; q++) { accC[i][q] = 0.f; accH[i][q] = 0.f; }

    const int arl = (lid & 7) + ((lid >> 3) & 1) * 8;
    const u32 aXor = (u32)((lid & 7) << 4);
    const u32 aK = (u32)((lid >> 4) * 16);
    const int lb = lid & 15;
    const u32 bXor = (u32)((lb & 7) << 4);
    const u32 bK = (u32)(((lb >> 3) & 1) * 16);
    const int brl = lb & 7;

    auto issue = [&](int c, int buf) {
        const uint4* Ahc = (c < n1) ? (Ah0 + (size_t)c * CHU) : (Ah1 + (size_t)(c - n1) * CHU);
        const uint4* Wc = Wf + (size_t)c * CHU;
        u32 d = sbase + (u32)buf * BSMAX;
        /* A: 32 rows x 128B = 256 uint4, 1 per thread */
        CPA(d + (u32)tid * 16u, (const void*)(Ahc + rowoff + tid));
        /* W: 128 rows x 128B = 1024 uint4, 4 per thread */
        u32 wb = d + 4096u;
#pragma unroll
        for (int i = 0; i < 4; i++)
            CPA(wb + (u32)(tid + i * NTHR) * 16u, (const void*)(Wc + tid + i * NTHR));
        CPCOMMIT();
    };

    issue(0, 0);
    if (nchunks > 1) issue(1, 1);
    if (nchunks > 2) issue(2, 2);
    for (int ci = 0; ci < nchunks; ci++) {
        if (ci + 2 < nchunks) { CPWAIT2(); }
        else if (ci + 1 < nchunks) { CPWAIT1(); }
        else { CPWAIT0(); }
        __syncthreads();   /* chunk ci landed; all warps done with chunk ci-1 */
        if (ci + 3 < nchunks) issue(ci + 3, (ci + 3) & 3);
        u32 b0 = sbase + (u32)(ci & 3) * BSMAX;
        u32 wB = b0 + 4096u;
#pragma unroll
        for (int ks = 0; ks < 4; ks++) {
            u32 ah[2][4];
            u32 ka = ((u32)(ks * 32) + aK) ^ aXor;
#pragma unroll
            for (int mf = 0; mf < 2; mf++)
                ldsm4(ah[mf], b0 + (u32)((mf * 16 + arl) * 128) + ka);
            u32 kb = ((u32)(ks * 32) + bK) ^ bXor;
            u32 wC[2], wH[2];
            ldsm2(wC, wB + (u32)((ncw + brl) * 128) + kb);
            ldsm2(wH, wB + (u32)((64 + ncw + brl) * 128) + kb);
#pragma unroll
            for (int mf = 0; mf < 2; mf++) {
                mma16816(accC[mf], ah[mf], wC);
                mma16816(accH[mf], ah[mf], wH);
            }
        }
    }
    __syncthreads();   /* all warps done with smem before next task reuses buffers */

    /* fused epilogue: s = sp + sig(c)*(act(h) - sp); fp32 + optional fp16 image */
#pragma unroll
    for (int mf = 0; mf < 2; mf++) {
        int rb = m0 + mf * 16 + (lid >> 2);
        int j = j0 + ncw + (lid & 3) * 2;
#pragma unroll
        for (int hr = 0; hr < 2; hr++) {
            int r = rb + hr * 8;
            float cv0 = accC[mf][hr * 2 + 0], cv1 = accC[mf][hr * 2 + 1];
            float hv0 = accH[mf][hr * 2 + 0], hv1 = accH[mf][hr * 2 + 1];
            float2 spv = *(const float2*)(sp + (size_t)r * HH + j);
            float s0 = spv.x + sigf(cv0) * (actf(hv0, act) - spv.x);
            float s1 = spv.y + sigf(cv1) * (actf(hv1, act) - spv.y);
            *(float2*)(Sout + (size_t)r * HH + j) = make_float2(s0, s1);
            if (imgH) {
                u32 off = SWZ((u32)((r & 127) * 128 + (j & 63) * 2));
                *(u32*)((char*)imgH + off) = pack2h(s0, s1);
            }
        }
    }
}

/* ---------------- persistent kernel: 256 CTAs, 2/SM ---------------- */
__global__ __launch_bounds__(NTHR, 2) void darts_mma(
    const float* __restrict__ inputs, const float* __restrict__ h0,
    float* __restrict__ out)
{
    extern __shared__ char smem[];
    const u32 sbase = smem_u32(smem);
    const int tid = threadIdx.x, bid = blockIdx.x;

    for (int t = 0; t < TT; t++) {
        const float* hp = t ? (out + (size_t)(t - 1) * BMH) : h0;

        /* Phase A: s0 over concat(x, h_prev), K=2048. 128 T32 tasks (bid<128), tanh. */
        if (bid < 128) {
            int m0 = (bid >> 4) * 32, nt = bid & 15, mtb = m0 >> 7, ro = (m0 & 127) * 8;
            run_tile(sbase,
                g_Xh + (size_t)mtb * 16 * CHU, g_Hh + (size_t)mtb * 16 * CHU,
                16, 32, ro,
                g_W0f + (size_t)nt * 32 * CHU,
                hp, g_S[0],
                g_Sih + ((size_t)mtb * 16 + nt) * CHU, 2, m0, nt * 64);
        }
        gridbar();

        /* Phase B: s1 = f(s0, Ws0, sigmoid). 128 T32 tasks (bid<128), K=1024. */
        if (bid < 128) {
            int m0 = (bid >> 4) * 32, nt = bid & 15, mtb = m0 >> 7, ro = (m0 & 127) * 8;
            run_tile(sbase,
                g_Sih + (size_t)mtb * 16 * CHU, (const uint4*)0,
                16, 16, ro,
                g_Wsf + (size_t)nt * 16 * CHU,
                g_S[0], g_S[1],
                g_Sih + ((size_t)(32 + mtb * 16 + nt)) * CHU, 0, m0, nt * 64);
        }
        gridbar();

        /* Phase C: s2 (bid<128) / s3 (bid>=128) from s1, relu, 256 T32 tasks.
           Plus bid<64: first half of s4 (identity). */
        {
            int op = bid >> 7, sub = bid & 127;
            int m0 = (sub >> 4) * 32, nt = sub & 15, mtb = m0 >> 7, ro = (m0 & 127) * 8;
            int os = 2 + op;
            run_tile(sbase,
                g_Sih + (size_t)(32 + mtb * 16) * CHU, (const uint4*)0,
                16, 16, ro,
                g_Wsf + (size_t)((1 + op) * 256 + nt * 16) * CHU,
                g_S[1], g_S[os],
                g_Sih + ((size_t)(os * 32 + mtb * 16 + nt)) * CHU, 1, m0, nt * 64);
            if (bid < 64) {
                int tt = bid;   /* s4 tasks 0..63 */
                int m4 = (tt >> 4) * 32, n4 = tt & 15, mb4 = m4 >> 7, ro4 = (m4 & 127) * 8;
                run_tile(sbase,
                    g_Sih + (size_t)(32 + mb4 * 16) * CHU, (const uint4*)0,
                    16, 16, ro4,
                    g_Wsf + (size_t)(3 * 256 + n4 * 16) * CHU,
                    g_S[1], g_S[4], (uint4*)0, 3, m4, n4 * 64);
            }
        }
        gridbar();

        /* Phase D: s5<-s2 (bid<128) / s7<-s3 (bid>=128), tanh, 256 T32 tasks. */
        {
            int op = bid >> 7, sub = bid & 127;
            int m0 = (sub >> 4) * 32, nt = sub & 15, mtb = m0 >> 7, ro = (m0 & 127) * 8;
            int is = op ? 3 : 2, os = op ? 7 : 5, wop = op ? 6 : 4;
            uint4* ih = op ? (uint4*)0 : g_Sih + ((size_t)(5 * 32 + mtb * 16 + nt)) * CHU;
            run_tile(sbase,
                g_Sih + (size_t)(is * 32 + mtb * 16) * CHU, (const uint4*)0,
                16, 16, ro,
                g_Wsf + (size_t)(wop * 256 + nt * 16) * CHU,
                g_S[is], g_S[os], ih, 2, m0, nt * 64);
        }
        gridbar();

        /* Phase E: s6<-s5 (bid<128, sigmoid) / s8<-s5 (bid>=128, relu), 256 tasks.
           Plus bid<64: second half of s4. */
        {
            int op = bid >> 7, sub = bid & 127;
            int m0 = (sub >> 4) * 32, nt = sub & 15, mtb = m0 >> 7, ro = (m0 & 127) * 8;
            int os = op ? 8 : 6, wop = op ? 7 : 5, a = op ? 1 : 0;
            run_tile(sbase,
                g_Sih + (size_t)(5 * 32 + mtb * 16) * CHU, (const uint4*)0,
                16, 16, ro,
                g_Wsf + (size_t)(wop * 256 + nt * 16) * CHU,
                g_S[5], g_S[os], (uint4*)0, a, m0, nt * 64);
            if (bid < 64) {
                int tt = 64 + bid;   /* s4 tasks 64..127 */
                int m4 = (tt >> 4) * 32, n4 = tt & 15, mb4 = m4 >> 7, ro4 = (m4 & 127) * 8;
                run_tile(sbase,
                    g_Sih + (size_t)(32 + mb4 * 16) * CHU, (const uint4*)0,
                    16, 16, ro4,
                    g_Wsf + (size_t)(3 * 256 + n4 * 16) * CHU,
                    g_S[1], g_S[4], (uint4*)0, 3, m4, n4 * 64);
            }
        }
        gridbar();

        /* Phase F: out[t] = mean(s1..s8); emit h image; convert x_{t+1} image.
           65536 threads x 4 floats. */
        {
            float* ot = out + (size_t)t * BMH;
            int uu = bid * NTHR + tid;
            int m = uu >> 8, j = (uu & 255) * 4;
            float a[4] = {0.f, 0.f, 0.f, 0.f};
#pragma unroll
            for (int s = 1; s < 9; s++) {
                float4 v = *(const float4*)(&g_S[s][(size_t)m * HH + j]);
                a[0] += v.x; a[1] += v.y; a[2] += v.z; a[3] += v.w;
            }
#pragma unroll
            for (int q = 0; q < 4; q++) a[q] *= 0.125f;
            *(float4*)(ot + (size_t)m * HH + j) = make_float4(a[0], a[1], a[2], a[3]);
            {
                u32 off = SWZ((u32)((m & 127) * 128 + (j & 63) * 2));
                size_t blk = ((size_t)(m >> 7) * 16 + (j >> 6)) * CHU;
                *(uint2*)((char*)(g_Hh + blk) + off) =
                    make_uint2(pack2h(a[0], a[1]), pack2h(a[2], a[3]));
            }
            if (t + 1 < TT) {
                float4 v = *(const float4*)(inputs + (size_t)(t + 1) * BMH + (size_t)m * HH + j);
                u32 off = SWZ((u32)((m & 127) * 128 + (j & 63) * 2));
                size_t blk = ((size_t)(m >> 7) * 16 + (j >> 6)) * CHU;
                *(uint2*)((char*)(g_Xh + blk) + off) =
                    make_uint2(pack2h(v.x, v.y), pack2h(v.z, v.w));
            }
        }
        gridbar();
    }
}

extern "C" void kernel_launch(void* const* d_in, const int* in_sizes, int n_in,
                              void* d_out, int out_size)
{
    const float* inputs = (const float*)d_in[0];  /* [T, B, 1024] */
    const float* h0     = (const float*)d_in[1];  /* [B, 1024]    */
    const float* W0     = (const float*)d_in[2];  /* [2048, 2048] */
    const float* Ws     = (const float*)d_in[3];  /* [8, 1024, 2048] */
    float* out = (float*)d_out;                   /* [T, B, 1024] */

    cudaFuncSetAttribute(darts_mma, cudaFuncAttributeMaxDynamicSharedMemorySize, SMEMT);

    prep<<<2816, PTHR>>>(inputs, h0, W0, Ws);
    darts_mma<<<GBLK, NTHR, SMEMT>>>(inputs, h0, out);
}